// round 14
// baseline (speedup 1.0000x reference)
#include <cuda_runtime.h>
#include <cuda_bf16.h>

// Shapes (fixed)
#define BB   8
#define NN   16384
#define SS   1024
#define TT   2
#define TPB  128
#define NPT  8
#define YT   512          // Y tile (smem) size

// Partial-min scratch (written fully every call; no reset needed)
#define P1N_OFF 0
#define P2N_OFF 262144
#define P1S_OFF 786432
#define P2S_OFF 1048576
__device__ float  g_pmin[1572864];      // 6 MB
__device__ float  g_csum[128];          // consistency block sums
__device__ double g_red[128];           // weighted partials from k_red

__device__ __forceinline__ unsigned long long bcast2(float f) {
    unsigned long long r;
    asm("mov.b64 %0, {%1, %1};" : "=l"(r) : "f"(f));
    return r;
}
__device__ __forceinline__ unsigned long long pack2(float lo, float hi) {
    unsigned long long r;
    asm("mov.b64 %0, {%1, %2};" : "=l"(r) : "f"(lo), "f"(hi));
    return r;
}
__device__ __forceinline__ unsigned long long ffma2(unsigned long long a,
                                                    unsigned long long b,
                                                    unsigned long long c) {
    unsigned long long d;
    asm("fma.rn.f32x2 %0, %1, %2, %3;" : "=l"(d) : "l"(a), "l"(b), "l"(c));
    return d;
}

__device__ __forceinline__ float block_reduce_sum(float v, float* sh) {
    #pragma unroll
    for (int o = 16; o > 0; o >>= 1) v += __shfl_down_sync(0xffffffffu, v, o);
    int lane = threadIdx.x & 31, w = threadIdx.x >> 5;
    if (lane == 0) sh[w] = v;
    __syncthreads();
    float r = 0.f;
    if (w == 0) {
        r = (lane < (int)(blockDim.x >> 5)) ? sh[lane] : 0.f;
        #pragma unroll
        for (int o = 16; o > 0; o >>= 1) r += __shfl_down_sync(0xffffffffu, r, o);
    }
    return r; // thread 0
}

// 1664 blocks x 128 threads; identical role layout to R13.
__global__ void __launch_bounds__(TPB) k_fused(
        const float* __restrict__ gt, const float* __restrict__ sp,
        const float* __restrict__ tgt, const float* __restrict__ tsp,
        const float* __restrict__ tm) {
    __shared__ __align__(16) unsigned long long ytile[YT * 4]; // 32 B/pt broadcast
    __shared__ float red[32];
    int blk = blockIdx.x;
    int tid = threadIdx.x;

    if (blk >= 1536) {
        // ---- consistency term ----
        int i = (blk - 1536) * TPB + tid;     // 0..16383
        int t = i >> 13;
        int rem = i & 8191;
        const float* p = sp + 3 * rem;
        float a = p[0], b = p[1], c = p[2];
        const float* M = tm + 9 * t;
        float acc = 0.f;
        #pragma unroll
        for (int e = 0; e < 3; e++) {
            float v = fmaf(a, M[e], fmaf(b, M[3 + e], c * M[6 + e]));
            float diff = v - tsp[(size_t)i * 3 + e];
            acc = fmaf(diff, diff, acc);
        }
        float bsum = block_reduce_sum(acc, red);
        if (tid == 0) g_csum[blk - 1536] = bsum;
        return;
    }

    const float* ysrc;   // 512 pts -> smem (broadcast-packed)
    const float* xsrc;   // 1024 pts -> regs (8/thread)
    float* outp;         // 1024 partial mins

    if (blk < 256) {                       // A: c1 n-side
        int b = blk >> 5, xc = (blk >> 1) & 15, yh = blk & 1;
        xsrc = gt + ((size_t)b * NN + (size_t)xc * 1024) * 3;
        ysrc = sp + ((size_t)b * SS + (size_t)yh * YT) * 3;
        outp = g_pmin + P1N_OFF + yh * 131072 + b * NN + xc * 1024;
    } else if (blk < 768) {                // B: c2 n-side
        int idx = blk - 256;
        int tb = idx >> 5, xc = (idx >> 1) & 15, yh = idx & 1;
        xsrc = tgt + ((size_t)tb * NN + (size_t)xc * 1024) * 3;
        ysrc = tsp + ((size_t)tb * SS + (size_t)yh * YT) * 3;
        outp = g_pmin + P2N_OFF + yh * 262144 + tb * NN + xc * 1024;
    } else if (blk < 1024) {               // C: c1 s-side
        int idx = blk - 768;
        int b = idx >> 5, yc = idx & 31;
        xsrc = sp + (size_t)b * SS * 3;
        ysrc = gt + ((size_t)b * NN + (size_t)yc * YT) * 3;
        outp = g_pmin + P1S_OFF + yc * 8192 + b * SS;
    } else {                               // D: c2 s-side
        int idx = blk - 1024;
        int tb = idx >> 5, yc = idx & 31;
        xsrc = tsp + (size_t)tb * SS * 3;
        ysrc = tgt + ((size_t)tb * NN + (size_t)yc * YT) * 3;
        outp = g_pmin + P2S_OFF + yc * 16384 + tb * SS;
    }

    // Broadcast-packed tile: per point {(-2x|-2x),(-2y|-2y),(-2z|-2z),(sq|sq)}
    for (int i = tid; i < YT; i += TPB) {
        const float* p = ysrc + 3 * i;
        float a = p[0], b = p[1], c = p[2];
        float sqv = fmaf(a, a, fmaf(b, b, c * c));
        ytile[4 * i + 0] = bcast2(-2.f * a);
        ytile[4 * i + 1] = bcast2(-2.f * b);
        ytile[4 * i + 2] = bcast2(-2.f * c);
        ytile[4 * i + 3] = bcast2(sqv);
    }
    __syncthreads();

    // 8 thread-private X points, packed into 4 f32x2 triples
    float a0[NPT], a1[NPT], a2[NPT], mn[NPT];
    #pragma unroll
    for (int k = 0; k < NPT; k++) {
        const float* p = xsrc + 3 * (tid + k * TPB);
        a0[k] = p[0]; a1[k] = p[1]; a2[k] = p[2];
        mn[k] = 3.4e38f;
    }
    unsigned long long x0p[4], x1p[4], x2p[4];
    #pragma unroll
    for (int kk = 0; kk < 4; kk++) {
        x0p[kk] = pack2(a0[2*kk], a0[2*kk+1]);
        x1p[kk] = pack2(a1[2*kk], a1[2*kk+1]);
        x2p[kk] = pack2(a2[2*kk], a2[2*kk+1]);
    }

    // Core loop per s: 2 LDS.128 + 12 FFMA2 (fma pipe) + 8 FMNMX (alu pipe)
    const ulonglong2* yt = (const ulonglong2*)ytile;
    #pragma unroll 4
    for (int s = 0; s < YT; s++) {
        ulonglong2 ya = yt[2 * s];       // (-2x|-2x), (-2y|-2y)
        ulonglong2 yb = yt[2 * s + 1];   // (-2z|-2z), (sq|sq)
        #pragma unroll
        for (int kk = 0; kk < 4; kk++) {
            unsigned long long v = ffma2(ya.x, x0p[kk], yb.y);
            v = ffma2(ya.y, x1p[kk], v);
            v = ffma2(yb.x, x2p[kk], v);
            float lo, hi;
            asm("mov.b64 {%0, %1}, %2;" : "=f"(lo), "=f"(hi) : "l"(v));
            mn[2*kk]   = fminf(mn[2*kk],   lo);
            mn[2*kk+1] = fminf(mn[2*kk+1], hi);
        }
    }

    #pragma unroll
    for (int k = 0; k < NPT; k++) {
        float sq = fmaf(a0[k], a0[k], fmaf(a1[k], a1[k], a2[k] * a2[k]));
        outp[tid + k * TPB] = mn[k] + sq;
    }
}

// Weighted reduction into 128 doubles.
#define W1N (1.0 / (131072.0 * 6.0))
#define W1S (1.0 / (8192.0   * 6.0))
#define W2N (1.0 / (262144.0 * 6.0))
#define W2S (1.0 / (16384.0  * 6.0))
#define WC  (1000.0 / 49152.0)

__global__ void k_red() {
    __shared__ double sh[8];
    int bid = blockIdx.x, tid = threadIdx.x;     // 128 blocks x 256 threads
    double acc = 0.0;
    {
        int base = bid * 1024;
        for (int j = tid; j < 1024; j += 256) {
            int i = base + j;
            acc += W1N * (double)fminf(g_pmin[P1N_OFF + i], g_pmin[P1N_OFF + 131072 + i]);
        }
    }
    {
        int base = bid * 2048;
        for (int j = tid; j < 2048; j += 256) {
            int i = base + j;
            acc += W2N * (double)fminf(g_pmin[P2N_OFF + i], g_pmin[P2N_OFF + 262144 + i]);
        }
    }
    if (tid < 64) {
        int r = bid * 64 + tid;
        float m = g_pmin[P1S_OFF + r];
        #pragma unroll
        for (int c = 1; c < 32; c++) m = fminf(m, g_pmin[P1S_OFF + c * 8192 + r]);
        acc += W1S * (double)m;
    }
    if (tid < 128) {
        int r = bid * 128 + tid;
        float m = g_pmin[P2S_OFF + r];
        #pragma unroll
        for (int c = 1; c < 32; c++) m = fminf(m, g_pmin[P2S_OFF + c * 16384 + r]);
        acc += W2S * (double)m;
    }
    #pragma unroll
    for (int o = 16; o > 0; o >>= 1) acc += __shfl_down_sync(0xffffffffu, acc, o);
    int lane = tid & 31, w = tid >> 5;
    if (lane == 0) sh[w] = acc;
    __syncthreads();
    if (tid == 0) {
        double t = WC * (double)g_csum[bid];
        for (int j = 0; j < 8; j++) t += sh[j];
        g_red[bid] = t;
    }
}

__global__ void k_final(float* __restrict__ out) {
    __shared__ double sh[4];
    double v = g_red[threadIdx.x];               // 128 threads
    #pragma unroll
    for (int o = 16; o > 0; o >>= 1) v += __shfl_down_sync(0xffffffffu, v, o);
    int lane = threadIdx.x & 31, w = threadIdx.x >> 5;
    if (lane == 0) sh[w] = v;
    __syncthreads();
    if (threadIdx.x == 0)
        out[0] = (float)(sh[0] + sh[1] + sh[2] + sh[3]);
}

extern "C" void kernel_launch(void* const* d_in, const int* in_sizes, int n_in,
                              void* d_out, int out_size) {
    const float* gt  = (const float*)d_in[0];  // [B,N,3]
    const float* sp  = (const float*)d_in[1];  // [B,S,3]
    const float* tgt = (const float*)d_in[2];  // [T,B,N,3]
    const float* tsp = (const float*)d_in[3];  // [T,B,S,3]
    const float* tm  = (const float*)d_in[4];  // [T,3,3]
    float* out = (float*)d_out;

    k_fused<<<1664, TPB>>>(gt, sp, tgt, tsp, tm);
    k_red<<<128, 256>>>();
    k_final<<<1, 128>>>(out);
}